// round 15
// baseline (speedup 1.0000x reference)
#include <cuda_runtime.h>
#include <cuda_bf16.h>
#include <math.h>
#include <stdint.h>

typedef unsigned long long ull;
typedef unsigned int uint;
typedef __nv_bfloat16 bf16;

// Problem constants
#define NTOT  32768
#define DIM   256
#define NB    16
#define VIS   512
#define MSK   1536
#define NV    (NB*VIS)   // 8192
#define NM    (NB*MSK)   // 24576
#define HID   128
#define NHEAD 8
#define DH    32

// weight hi/lo layout offsets (elements)
#define WOFF_PE2 0
#define WOFF_Q   65536
#define WOFF_K   131072
#define WOFF_V   196608
#define WOFF_O   262144
#define WOFF_D1  327680          // 128x256
#define WOFF_D2  360448          // 128x128
#define WTOT     376832

// ---------------- scratch -----------------------------------------------------
__device__ float g_X[NTOT*DIM];
__device__ float g_AO[NM*DIM];
__device__ float g_H1[NTOT*HID];
__device__ float g_H2[NTOT*HID];
__device__ float g_biasKV[512];
__device__ int   g_mm[6];
__device__ bf16 g_Ghi[NTOT*DIM], g_Glo[NTOT*DIM];
__device__ bf16 g_Xhi[NTOT*DIM], g_Xlo[NTOT*DIM];
__device__ bf16 g_Qhi[NM*DIM],  g_Qlo[NM*DIM];
__device__ bf16 g_Khi[NV*DIM],  g_Klo[NV*DIM];
__device__ bf16 g_Vhi[NV*DIM],  g_Vlo[NV*DIM];
__device__ bf16 g_Ohi[NM*DIM],  g_Olo[NM*DIM];
__device__ bf16 g_MFhi[NM*DIM], g_MFlo[NM*DIM];
__device__ bf16 g_G1hi[NTOT*HID], g_G1lo[NTOT*HID];
__device__ bf16 g_Whi[WTOT], g_Wlo[WTOT];

// ---------------- helpers -----------------------------------------------------
__device__ __forceinline__ int f2ord(float f){ int i=__float_as_int(f); return i>=0 ? i : (i^0x7fffffff); }
__device__ __forceinline__ float ord2f(int i){ return __int_as_float(i>=0 ? i : (i^0x7fffffff)); }
__device__ __forceinline__ float gelu(float x){ return 0.5f*x*(1.0f+erff(x*0.70710678118654752f)); }
__device__ __forceinline__ uint pkbf(float a, float b){
    __nv_bfloat162 t=__floats2bfloat162_rn(a,b); return *(uint*)&t;
}
__device__ __forceinline__ uint32_t smem_u32(const void* p){
    uint32_t a; asm("{ .reg .u64 t; cvta.to.shared.u64 t, %1; cvt.u32.u64 %0, t; }" : "=r"(a) : "l"(p)); return a;
}
#define LDM4(r0,r1,r2,r3,addr) \
    asm volatile("ldmatrix.sync.aligned.m8n8.x4.shared.b16 {%0,%1,%2,%3}, [%4];" \
        : "=r"(r0),"=r"(r1),"=r"(r2),"=r"(r3) : "r"(addr))
#define LDM4T(r0,r1,r2,r3,addr) \
    asm volatile("ldmatrix.sync.aligned.m8n8.x4.trans.shared.b16 {%0,%1,%2,%3}, [%4];" \
        : "=r"(r0),"=r"(r1),"=r"(r2),"=r"(r3) : "r"(addr))
#define MMA16816(d, a, b) \
    asm volatile("mma.sync.aligned.m16n8k16.row.col.f32.bf16.bf16.f32 " \
        "{%0,%1,%2,%3}, {%4,%5,%6,%7}, {%8,%9}, {%0,%1,%2,%3};" \
        : "+f"((d)[0]),"+f"((d)[1]),"+f"((d)[2]),"+f"((d)[3]) \
        : "r"((a)[0]),"r"((a)[1]),"r"((a)[2]),"r"((a)[3]),"r"((b)[0]),"r"((b)[1]))
#define CPA16(dst,src) asm volatile("cp.async.cg.shared.global [%0], [%1], 16;"::"r"(dst),"l"(src))
#define CPCOMMIT() asm volatile("cp.async.commit_group;")
#define CPWAIT0() asm volatile("cp.async.wait_group 0;")

// ================= min/max reduction =========================================
__global__ void mm_kernel(const float* __restrict__ coord){
    float mn0=1e30f,mn1=1e30f,mn2=1e30f,mx0=-1e30f,mx1=-1e30f,mx2=-1e30f;
    for(int p=blockIdx.x*blockDim.x+threadIdx.x; p<NTOT; p+=gridDim.x*blockDim.x){
        float a=coord[p*3+0], b=coord[p*3+1], c=coord[p*3+2];
        mn0=fminf(mn0,a); mx0=fmaxf(mx0,a);
        mn1=fminf(mn1,b); mx1=fmaxf(mx1,b);
        mn2=fminf(mn2,c); mx2=fmaxf(mx2,c);
    }
    for(int o=16;o;o>>=1){
        mn0=fminf(mn0,__shfl_xor_sync(0xffffffffu,mn0,o));
        mn1=fminf(mn1,__shfl_xor_sync(0xffffffffu,mn1,o));
        mn2=fminf(mn2,__shfl_xor_sync(0xffffffffu,mn2,o));
        mx0=fmaxf(mx0,__shfl_xor_sync(0xffffffffu,mx0,o));
        mx1=fmaxf(mx1,__shfl_xor_sync(0xffffffffu,mx1,o));
        mx2=fmaxf(mx2,__shfl_xor_sync(0xffffffffu,mx2,o));
    }
    if((threadIdx.x&31)==0){
        atomicMin(&g_mm[0],f2ord(mn0)); atomicMin(&g_mm[1],f2ord(mn1)); atomicMin(&g_mm[2],f2ord(mn2));
        atomicMax(&g_mm[3],f2ord(mx0)); atomicMax(&g_mm[4],f2ord(mx1)); atomicMax(&g_mm[5],f2ord(mx2));
    }
}

// ================= weight prep (+ g_mm init) ==================================
__global__ void prep_weights_kernel(const float* __restrict__ w2, const float* __restrict__ wq,
                                    const float* __restrict__ wk, const float* __restrict__ wv,
                                    const float* __restrict__ wo, const float* __restrict__ dw1,
                                    const float* __restrict__ dw2,
                                    const float* __restrict__ bk, const float* __restrict__ bv){
    int i=blockIdx.x*blockDim.x+threadIdx.x;
    if(i<3) g_mm[i]=0x7fffffff;
    else if(i<6) g_mm[i]=0x80000000;
    if(i<512) g_biasKV[i] = (i<256)? bk[i] : bv[i-256];
    if(i>=WTOT) return;
    const float* src; int j;
    if(i<WOFF_Q){ src=w2; j=i; }
    else if(i<WOFF_K){ src=wq; j=i-WOFF_Q; }
    else if(i<WOFF_V){ src=wk; j=i-WOFF_K; }
    else if(i<WOFF_O){ src=wv; j=i-WOFF_V; }
    else if(i<WOFF_D1){ src=wo; j=i-WOFF_O; }
    else if(i<WOFF_D2){ src=dw1; j=i-WOFF_D1; }
    else { src=dw2; j=i-WOFF_D2; }
    float x=src[j];
    bf16 h=__float2bfloat16_rn(x);
    g_Whi[i]=h;
    g_Wlo[i]=__float2bfloat16_rn(x-__bfloat162float(h));
}

// ================= pos-embed stage 1 =========================================
__global__ void pe_stage1_kernel(const float* __restrict__ coord,
                                 const float* __restrict__ w1, const float* __restrict__ b1,
                                 const float* __restrict__ gam, const float* __restrict__ bet){
    int w=threadIdx.x>>5, lane=threadIdx.x&31;
    int p=blockIdx.x*8+w;
    float lo0=ord2f(g_mm[0]), lo1=ord2f(g_mm[1]), lo2=ord2f(g_mm[2]);
    float s0=fmaxf(ord2f(g_mm[3])-lo0,1.0f);
    float s1=fmaxf(ord2f(g_mm[4])-lo1,1.0f);
    float s2=fmaxf(ord2f(g_mm[5])-lo2,1.0f);
    float c0=(coord[p*3+0]-lo0)/s0;
    float c1=(coord[p*3+1]-lo1)/s1;
    float c2=(coord[p*3+2]-lo2)/s2;
    float v[8]; float s=0.f, ss=0.f;
#pragma unroll
    for(int j=0;j<8;j++){
        int d=lane+32*j;
        float h=c0*w1[d*3+0]+c1*w1[d*3+1]+c2*w1[d*3+2]+b1[d];
        v[j]=h; s+=h; ss+=h*h;
    }
    for(int o=16;o;o>>=1){ s+=__shfl_xor_sync(0xffffffffu,s,o); ss+=__shfl_xor_sync(0xffffffffu,ss,o); }
    float mean=s*(1.0f/256.0f);
    float rstd=rsqrtf(ss*(1.0f/256.0f)-mean*mean+1e-5f);
#pragma unroll
    for(int j=0;j<8;j++){
        int d=lane+32*j;
        float t=(v[j]-mean)*rstd*gam[d]+bet[d];
        float g=gelu(t);
        bf16 h=__float2bfloat16_rn(g);
        g_Ghi[(size_t)p*DIM+d]=h;
        g_Glo[(size_t)p*DIM+d]=__float2bfloat16_rn(g-__bfloat162float(h));
    }
}

// ================= bf16x3 mma GEMM (2-stage, 2 CTAs/SM) ======================
// gatherMode: 0 direct, 1 masked idx, 2 visible idx, 3 mixed X/MF (decoder)
// epiMode: 0 plain, 1 +enc/mtok, 2 gelu
// kvSplit: cols>=256 route hi/lo to vhi/vlo (stride 256), cols<256 -> Chi/Clo
#define KSTR 40
#define TILEB (128*KSTR*2)
#define BUFB  (4*TILEB)
__global__ void __launch_bounds__(256,2) mma_gemm2_kernel(
        const bf16* __restrict__ Ahi, const bf16* __restrict__ Alo,
        const bf16* __restrict__ A2hi, const bf16* __restrict__ A2lo,
        const bf16* __restrict__ Bhi, const bf16* __restrict__ Blo,
        const float* __restrict__ bias, float* __restrict__ Cf,
        bf16* __restrict__ Chi, bf16* __restrict__ Clo,
        bf16* __restrict__ vhi, bf16* __restrict__ vlo,
        int gatherMode, int epiMode, int kchunks, int strideC, int kvSplit,
        const float* __restrict__ encoded, const float* __restrict__ mtok){
    extern __shared__ char dsm[];
    const int tid=threadIdx.x, lane=tid&31, wid=tid>>5;
    const int m0=blockIdx.x*128, n0=blockIdx.y*128;
    const int wm=(wid>>2)*64, wn=(wid&3)*32;
    const int K=kchunks*32;

    const int lrow=tid>>1, hc=(tid&1)*16;
    int cm=m0+lrow;
    const bf16 *aH, *aL;
    if(gatherMode==1){ int r=(cm/1536)*2048+512+(cm%1536); aH=Ahi+(size_t)r*K+hc; aL=Alo+(size_t)r*K+hc; }
    else if(gatherMode==2){ int r=(cm>>9)*2048+(cm&511); aH=Ahi+(size_t)r*K+hc; aL=Alo+(size_t)r*K+hc; }
    else if(gatherMode==3){
        int off=cm&2047;
        if(off<VIS){ aH=Ahi+(size_t)cm*K+hc; aL=Alo+(size_t)cm*K+hc; }
        else { int r=(cm>>11)*MSK+off-VIS; aH=A2hi+(size_t)r*K+hc; aL=A2lo+(size_t)r*K+hc; }
    }
    else { aH=Ahi+(size_t)cm*K+hc; aL=Alo+(size_t)cm*K+hc; }
    const bf16* bH=Bhi+(size_t)(n0+lrow)*K+hc;
    const bf16* bL=Blo+(size_t)(n0+lrow)*K+hc;
    const uint32_t sbase=smem_u32(dsm);
    const uint32_t st_off=(uint32_t)((lrow*KSTR+hc)*2);

    const int a_r=wm+(lane&7)+((lane>>3)&1)*8;
    const int a_c=(lane>>4)*8;
    const int b_r=wn+(lane&7)+(lane>>4)*8;
    const int b_c=((lane>>3)&1)*8;

    float acc[4][4][4];
#pragma unroll
    for(int i=0;i<4;i++)
#pragma unroll
        for(int j=0;j<4;j++)
#pragma unroll
            for(int k=0;k<4;k++) acc[i][j][k]=0.f;

#define LOAD_CHUNK(c,buf) do{ \
        uint32_t b0=sbase+(buf)*BUFB; \
        const bf16* p0=aH+(c)*32; CPA16(b0+st_off,p0); CPA16(b0+st_off+16,p0+8); \
        const bf16* p1=aL+(c)*32; CPA16(b0+TILEB+st_off,p1); CPA16(b0+TILEB+st_off+16,p1+8); \
        const bf16* p2=bH+(c)*32; CPA16(b0+2*TILEB+st_off,p2); CPA16(b0+2*TILEB+st_off+16,p2+8); \
        const bf16* p3=bL+(c)*32; CPA16(b0+3*TILEB+st_off,p3); CPA16(b0+3*TILEB+st_off+16,p3+8); \
        CPCOMMIT(); }while(0)

    LOAD_CHUNK(0,0);
    int buf=0;
    for(int c=0;c<kchunks;c++){
        CPWAIT0();              // chunk c landed (only group in flight)
        __syncthreads();        // all warps done with buf^1 (computed at c-1)
        if(c+1<kchunks) LOAD_CHUNK(c+1,buf^1);
        uint32_t b0=sbase+buf*BUFB;
#pragma unroll
        for(int ks=0;ks<2;ks++){
            uint bh[4][2], bl[4][2];
#pragma unroll
            for(int bt=0;bt<2;bt++){
                uint32_t off=(uint32_t)(((b_r+bt*16)*KSTR + b_c + ks*16)*2);
                uint r0,r1,r2,r3;
                LDM4(r0,r1,r2,r3, b0+2*TILEB+off);
                bh[2*bt][0]=r0; bh[2*bt][1]=r1; bh[2*bt+1][0]=r2; bh[2*bt+1][1]=r3;
                LDM4(r0,r1,r2,r3, b0+3*TILEB+off);
                bl[2*bt][0]=r0; bl[2*bt][1]=r1; bl[2*bt+1][0]=r2; bl[2*bt+1][1]=r3;
            }
#pragma unroll
            for(int mt=0;mt<4;mt++){
                uint ah[4], al[4];
                uint32_t off=(uint32_t)(((a_r+mt*16)*KSTR + a_c + ks*16)*2);
                LDM4(ah[0],ah[1],ah[2],ah[3], b0+off);
                LDM4(al[0],al[1],al[2],al[3], b0+TILEB+off);
#pragma unroll
                for(int nt=0;nt<4;nt++){
                    MMA16816(acc[mt][nt], ah, bh[nt]);
                    MMA16816(acc[mt][nt], ah, bl[nt]);
                    MMA16816(acc[mt][nt], al, bh[nt]);
                }
            }
        }
        buf^=1;
    }
#undef LOAD_CHUNK

#pragma unroll
    for(int mt=0;mt<4;mt++){
        int r0=m0+wm+mt*16+(lane>>2);
        int r1=r0+8;
        const float *ap0=0,*ap1=0;
        if(epiMode==1){
            int off0=r0&2047; ap0=(off0<VIS)? encoded+(size_t)((r0>>11)*VIS+off0)*DIM : mtok;
            int off1=r1&2047; ap1=(off1<VIS)? encoded+(size_t)((r1>>11)*VIS+off1)*DIM : mtok;
        }
#pragma unroll
        for(int nt=0;nt<4;nt++){
            int cc=n0+wn+nt*8+(lane&3)*2;
            float b0v=bias[cc], b1v=bias[cc+1];
            float v00=acc[mt][nt][0]+b0v, v01=acc[mt][nt][1]+b1v;
            float v10=acc[mt][nt][2]+b0v, v11=acc[mt][nt][3]+b1v;
            if(epiMode==1){ v00+=ap0[cc]; v01+=ap0[cc+1]; v10+=ap1[cc]; v11+=ap1[cc+1]; }
            else if(epiMode==2){ v00=gelu(v00); v01=gelu(v01); v10=gelu(v10); v11=gelu(v11); }
            bf16* dhi=Chi; bf16* dlo=Clo; int wc=cc;
            if(kvSplit && n0>=256){ dhi=vhi; dlo=vlo; wc=cc-256; }
            else if(Cf){
                *(float2*)(Cf+(size_t)r0*strideC+cc)=make_float2(v00,v01);
                *(float2*)(Cf+(size_t)r1*strideC+cc)=make_float2(v10,v11);
            }
            if(dhi){
                bf16 h00=__float2bfloat16_rn(v00), h01=__float2bfloat16_rn(v01);
                bf16 h10=__float2bfloat16_rn(v10), h11=__float2bfloat16_rn(v11);
                __nv_bfloat162 hp0; hp0.x=h00; hp0.y=h01;
                __nv_bfloat162 hp1; hp1.x=h10; hp1.y=h11;
                *(__nv_bfloat162*)(dhi+(size_t)r0*strideC+wc)=hp0;
                *(__nv_bfloat162*)(dhi+(size_t)r1*strideC+wc)=hp1;
                __nv_bfloat162 lp0, lp1;
                lp0.x=__float2bfloat16_rn(v00-__bfloat162float(h00));
                lp0.y=__float2bfloat16_rn(v01-__bfloat162float(h01));
                lp1.x=__float2bfloat16_rn(v10-__bfloat162float(h10));
                lp1.y=__float2bfloat16_rn(v11-__bfloat162float(h11));
                *(__nv_bfloat162*)(dlo+(size_t)r0*strideC+wc)=lp0;
                *(__nv_bfloat162*)(dlo+(size_t)r1*strideC+wc)=lp1;
            }
        }
    }
}

// ================= mma flash attention (copy-only staging) ====================
#define QPAD 40
#define VP   40
#define SOFF_QH 0
#define SOFF_QL 10240
#define SOFF_KH 20480
#define SOFF_KL 30720
#define SOFF_VH 40960
#define SOFF_VL 51200
#define ATT_SMEM 61440
#define ATT_SCALE 0.17677669529663687f
__global__ void __launch_bounds__(256,1) attn_mma_kernel(){
    extern __shared__ char dsm[];
    const int tid=threadIdx.x, lane=tid&31, wid=tid>>5;
    const int qt=blockIdx.x, h=blockIdx.y, b=blockIdx.z;
    const uint32_t sb=smem_u32(dsm);

    {
        int row=tid>>1, half=tid&1;
        size_t g=(size_t)(b*MSK+qt*128+row)*DIM + h*DH + half*16;
        uint soff=(uint)((row*QPAD+half*16)*2);
        const uint4* s0=(const uint4*)(g_Qhi+g);
        uint4* d0=(uint4*)(dsm+SOFF_QH+soff); d0[0]=s0[0]; d0[1]=s0[1];
        const uint4* s1=(const uint4*)(g_Qlo+g);
        uint4* d1=(uint4*)(dsm+SOFF_QL+soff); d1[0]=s1[0]; d1[1]=s1[1];
    }
    __syncthreads();

    const int wm=wid*16;
    const int a_r=wm+(lane&7)+((lane>>3)&1)*8;
    const int a_c=(lane>>4)*8;
    uint qh[2][4], ql[2][4];
#pragma unroll
    for(int ks=0;ks<2;ks++){
        uint off=(uint)((a_r*QPAD + a_c + ks*16)*2);
        LDM4(qh[ks][0],qh[ks][1],qh[ks][2],qh[ks][3], sb+SOFF_QH+off);
        LDM4(ql[ks][0],ql[ks][1],ql[ks][2],ql[ks][3], sb+SOFF_QL+off);
    }

    const int b_r=(lane&7)+(lane>>4)*8;
    const int b_c=((lane>>3)&1)*8;
    const int v_r=(lane&7)+((lane>>3)&1)*8;
    const int v_c=(lane>>4)*8;
    float accO[4][4];
#pragma unroll
    for(int i=0;i<4;i++)
#pragma unroll
        for(int j=0;j<4;j++) accO[i][j]=0.f;
    float l0=0.f, l1=0.f;

    for(int kt=0;kt<4;kt++){
        __syncthreads();
        {
            int row=tid>>1, half=tid&1;
            size_t g=(size_t)(b*VIS+kt*128+row)*DIM + h*DH + half*16;
            uint soff=(uint)((row*QPAD+half*16)*2);
            const uint4* s0=(const uint4*)(g_Khi+g);
            uint4* d0=(uint4*)(dsm+SOFF_KH+soff); d0[0]=s0[0]; d0[1]=s0[1];
            const uint4* s1=(const uint4*)(g_Klo+g);
            uint4* d1=(uint4*)(dsm+SOFF_KL+soff); d1[0]=s1[0]; d1[1]=s1[1];
            uint voff=(uint)((row*VP+half*16)*2);
            const uint4* s2=(const uint4*)(g_Vhi+g);
            uint4* d2=(uint4*)(dsm+SOFF_VH+voff); d2[0]=s2[0]; d2[1]=s2[1];
            const uint4* s3=(const uint4*)(g_Vlo+g);
            uint4* d3=(uint4*)(dsm+SOFF_VL+voff); d3[0]=s3[0]; d3[1]=s3[1];
        }
        __syncthreads();

        float acc[16][4];
#pragma unroll
        for(int i=0;i<16;i++)
#pragma unroll
            for(int j=0;j<4;j++) acc[i][j]=0.f;
#pragma unroll
        for(int ks=0;ks<2;ks++){
#pragma unroll
            for(int bt=0;bt<8;bt++){
                uint off=(uint)(((b_r+bt*16)*QPAD + b_c + ks*16)*2);
                uint kh0[2],kh1[2],kl0[2],kl1[2];
                { uint r0,r1,r2,r3; LDM4(r0,r1,r2,r3, sb+SOFF_KH+off);
                  kh0[0]=r0; kh0[1]=r1; kh1[0]=r2; kh1[1]=r3; }
                { uint r0,r1,r2,r3; LDM4(r0,r1,r2,r3, sb+SOFF_KL+off);
                  kl0[0]=r0; kl0[1]=r1; kl1[0]=r2; kl1[1]=r3; }
                MMA16816(acc[2*bt],   qh[ks], kh0);
                MMA16816(acc[2*bt],   qh[ks], kl0);
                MMA16816(acc[2*bt],   ql[ks], kh0);
                MMA16816(acc[2*bt+1], qh[ks], kh1);
                MMA16816(acc[2*bt+1], qh[ks], kl1);
                MMA16816(acc[2*bt+1], ql[ks], kh1);
            }
        }
#pragma unroll
        for(int k2=0;k2<8;k2++){
            float p[8];
#pragma unroll
            for(int j=0;j<4;j++) p[j]  =__expf(fminf(acc[2*k2][j]  *ATT_SCALE,80.f));
#pragma unroll
            for(int j=0;j<4;j++) p[4+j]=__expf(fminf(acc[2*k2+1][j]*ATT_SCALE,80.f));
            l0 += p[0]+p[1]+p[4]+p[5];
            l1 += p[2]+p[3]+p[6]+p[7];
            uint ph[4], pl[4];
            ph[0]=pkbf(p[0],p[1]); ph[1]=pkbf(p[2],p[3]);
            ph[2]=pkbf(p[4],p[5]); ph[3]=pkbf(p[6],p[7]);
            float r[8];
#pragma unroll
            for(int j=0;j<8;j++){
                bf16 hh=__float2bfloat16_rn(p[j]);
                r[j]=p[j]-__bfloat162float(hh);
            }
            pl[0]=pkbf(r[0],r[1]); pl[1]=pkbf(r[2],r[3]);
            pl[2]=pkbf(r[4],r[5]); pl[3]=pkbf(r[6],r[7]);
            uint vh2[4][2], vl2[4][2];
#pragma unroll
            for(int nh=0;nh<2;nh++){
                uint off=(uint)(((v_r+k2*16)*VP + v_c + nh*16)*2);
                uint r0,r1,r2,r3;
                LDM4T(r0,r1,r2,r3, sb+SOFF_VH+off);
                vh2[2*nh][0]=r0; vh2[2*nh][1]=r1; vh2[2*nh+1][0]=r2; vh2[2*nh+1][1]=r3;
                LDM4T(r0,r1,r2,r3, sb+SOFF_VL+off);
                vl2[2*nh][0]=r0; vl2[2*nh][1]=r1; vl2[2*nh+1][0]=r2; vl2[2*nh+1][1]=r3;
            }
#pragma unroll
            for(int nt=0;nt<4;nt++){
                MMA16816(accO[nt], ph, vh2[nt]);
                MMA16816(accO[nt], ph, vl2[nt]);
                MMA16816(accO[nt], pl, vh2[nt]);
            }
        }
    }

    l0 += __shfl_xor_sync(0xffffffffu,l0,1); l0 += __shfl_xor_sync(0xffffffffu,l0,2);
    l1 += __shfl_xor_sync(0xffffffffu,l1,1); l1 += __shfl_xor_sync(0xffffffffu,l1,2);
    float inv0=1.0f/l0, inv1=1.0f/l1;
    int row0=b*MSK+qt*128+wm+(lane>>2);
    int row1=row0+8;
#pragma unroll
    for(int nt=0;nt<4;nt++){
        int col=h*DH+nt*8+(lane&3)*2;
        float v00=accO[nt][0]*inv0, v01=accO[nt][1]*inv0;
        float v10=accO[nt][2]*inv1, v11=accO[nt][3]*inv1;
        bf16 h00=__float2bfloat16_rn(v00), h01=__float2bfloat16_rn(v01);
        bf16 h10=__float2bfloat16_rn(v10), h11=__float2bfloat16_rn(v11);
        __nv_bfloat162 hp0; hp0.x=h00; hp0.y=h01;
        __nv_bfloat162 hp1; hp1.x=h10; hp1.y=h11;
        *(__nv_bfloat162*)(g_Ohi+(size_t)row0*DIM+col)=hp0;
        *(__nv_bfloat162*)(g_Ohi+(size_t)row1*DIM+col)=hp1;
        __nv_bfloat162 lp0, lp1;
        lp0.x=__float2bfloat16_rn(v00-__bfloat162float(h00));
        lp0.y=__float2bfloat16_rn(v01-__bfloat162float(h01));
        lp1.x=__float2bfloat16_rn(v10-__bfloat162float(h10));
        lp1.y=__float2bfloat16_rn(v11-__bfloat162float(h11));
        *(__nv_bfloat162*)(g_Olo+(size_t)row0*DIM+col)=lp0;
        *(__nv_bfloat162*)(g_Olo+(size_t)row1*DIM+col)=lp1;
    }
}

// ================= residual LN -> MF hi/lo ====================================
__global__ void mf_ln_kernel(const float* __restrict__ gam, const float* __restrict__ bet){
    int w=threadIdx.x>>5, lane=threadIdx.x&31;
    int row=blockIdx.x*8+w;
    int pt=(row/1536)*2048+512+(row%1536);
    float v[8]; float s=0.f, ss=0.f;
#pragma unroll
    for(int j=0;j<8;j++){
        int d=lane+32*j;
        float x=g_X[(size_t)pt*DIM+d]+g_AO[(size_t)row*DIM+d];
        v[j]=x; s+=x; ss+=x*x;
    }
    for(int o=16;o;o>>=1){ s+=__shfl_xor_sync(0xffffffffu,s,o); ss+=__shfl_xor_sync(0xffffffffu,ss,o); }
    float mean=s*(1.0f/256.0f);
    float rstd=rsqrtf(ss*(1.0f/256.0f)-mean*mean+1e-5f);
#pragma unroll
    for(int j=0;j<8;j++){
        int d=lane+32*j;
        float t=(v[j]-mean)*rstd*gam[d]+bet[d];
        bf16 h=__float2bfloat16_rn(t);
        g_MFhi[(size_t)row*DIM+d]=h;
        g_MFlo[(size_t)row*DIM+d]=__float2bfloat16_rn(t-__bfloat162float(h));
    }
}

// ================= decoder stage: LN(H1)+gelu -> G1 hi/lo =====================
__global__ void ln_gelu_kernel(const float* __restrict__ gam, const float* __restrict__ bet){
    int w=threadIdx.x>>5, lane=threadIdx.x&31;
    int row=blockIdx.x*8+w;
    float4 v=((const float4*)(g_H1+(size_t)row*HID))[lane];
    float s=v.x+v.y+v.z+v.w;
    float ss=v.x*v.x+v.y*v.y+v.z*v.z+v.w*v.w;
    for(int o=16;o;o>>=1){ s+=__shfl_xor_sync(0xffffffffu,s,o); ss+=__shfl_xor_sync(0xffffffffu,ss,o); }
    float mean=s*(1.0f/128.0f);
    float rstd=rsqrtf(ss*(1.0f/128.0f)-mean*mean+1e-5f);
    float g4[4]; float vv[4]={v.x,v.y,v.z,v.w};
#pragma unroll
    for(int j=0;j<4;j++){
        int d=lane*4+j;
        g4[j]=gelu((vv[j]-mean)*rstd*gam[d]+bet[d]);
    }
    bf16* hp=g_G1hi+(size_t)row*HID+lane*4;
    bf16* lp=g_G1lo+(size_t)row*HID+lane*4;
#pragma unroll
    for(int j=0;j<2;j++){
        __nv_bfloat162 h2v, l2v;
        float a=g4[2*j], b2=g4[2*j+1];
        bf16 ha=__float2bfloat16_rn(a), hb=__float2bfloat16_rn(b2);
        h2v.x=ha; h2v.y=hb;
        l2v.x=__float2bfloat16_rn(a-__bfloat162float(ha));
        l2v.y=__float2bfloat16_rn(b2-__bfloat162float(hb));
        *(__nv_bfloat162*)(hp+2*j)=h2v;
        *(__nv_bfloat162*)(lp+2*j)=l2v;
    }
}

// ================= final: out = H2 @ w3^T + b3 ================================
__global__ void final_kernel(const float* __restrict__ w3, const float* __restrict__ b3,
                             float* __restrict__ out){
    int w=threadIdx.x>>5, lane=threadIdx.x&31;
    int p=blockIdx.x*8+w;
    const float* h2=g_H2+(size_t)p*HID;
    float x0=h2[lane], x1=h2[lane+32], x2=h2[lane+64], x3=h2[lane+96];
    float q[4];
#pragma unroll
    for(int j=0;j<4;j++){
        const float* wj=w3+j*HID;
        q[j]=x0*wj[lane]+x1*wj[lane+32]+x2*wj[lane+64]+x3*wj[lane+96];
        for(int o=16;o;o>>=1) q[j]+=__shfl_xor_sync(0xffffffffu,q[j],o);
    }
    if(lane==0)
        *(float4*)(out+(size_t)p*4)=make_float4(q[0]+b3[0],q[1]+b3[1],q[2]+b3[2],q[3]+b3[3]);
}

// -----------------------------------------------------------------------------
extern "C" void kernel_launch(void* const* d_in, const int* in_sizes, int n_in,
                              void* d_out, int out_size){
    const float* encoded   =(const float*)d_in[0];
    const float* coord     =(const float*)d_in[1];
    const float* mask_token=(const float*)d_in[2];
    const float* pe_w1     =(const float*)d_in[3];
    const float* pe_b1     =(const float*)d_in[4];
    const float* pe_g      =(const float*)d_in[5];
    const float* pe_be     =(const float*)d_in[6];
    const float* pe_w2     =(const float*)d_in[7];
    const float* pe_b2     =(const float*)d_in[8];
    const float* wq        =(const float*)d_in[9];
    const float* bq        =(const float*)d_in[10];
    const float* wk        =(const float*)d_in[11];
    const float* bk        =(const float*)d_in[12];
    const float* wv        =(const float*)d_in[13];
    const float* bv        =(const float*)d_in[14];
    const float* wo        =(const float*)d_in[15];
    const float* bo        =(const float*)d_in[16];
    const float* an_g      =(const float*)d_in[17];
    const float* an_b      =(const float*)d_in[18];
    const float* d_w1      =(const float*)d_in[19];
    const float* d_b1      =(const float*)d_in[20];
    const float* d_g       =(const float*)d_in[21];
    const float* d_be      =(const float*)d_in[22];
    const float* d_w2      =(const float*)d_in[23];
    const float* d_b2      =(const float*)d_in[24];
    const float* d_w3      =(const float*)d_in[25];
    const float* d_b3      =(const float*)d_in[26];
    float* out=(float*)d_out;
    (void)in_sizes; (void)n_in; (void)out_size;

    float *pX=0,*pAO=0,*pH1=0,*pH2=0,*pBKV=0;
    bf16 *pGhi=0,*pGlo=0,*pXhi=0,*pXlo=0,*pQhi=0,*pQlo=0,*pKhi=0,*pKlo=0,*pVhi=0,*pVlo=0;
    bf16 *pOhi=0,*pOlo=0,*pWhi=0,*pWlo=0,*pMFhi=0,*pMFlo=0,*pG1hi=0,*pG1lo=0;
    cudaGetSymbolAddress((void**)&pX,  g_X);
    cudaGetSymbolAddress((void**)&pAO, g_AO);
    cudaGetSymbolAddress((void**)&pH1, g_H1);
    cudaGetSymbolAddress((void**)&pH2, g_H2);
    cudaGetSymbolAddress((void**)&pBKV,g_biasKV);
    cudaGetSymbolAddress((void**)&pGhi,g_Ghi);
    cudaGetSymbolAddress((void**)&pGlo,g_Glo);
    cudaGetSymbolAddress((void**)&pXhi,g_Xhi);
    cudaGetSymbolAddress((void**)&pXlo,g_Xlo);
    cudaGetSymbolAddress((void**)&pQhi,g_Qhi);
    cudaGetSymbolAddress((void**)&pQlo,g_Qlo);
    cudaGetSymbolAddress((void**)&pKhi,g_Khi);
    cudaGetSymbolAddress((void**)&pKlo,g_Klo);
    cudaGetSymbolAddress((void**)&pVhi,g_Vhi);
    cudaGetSymbolAddress((void**)&pVlo,g_Vlo);
    cudaGetSymbolAddress((void**)&pOhi,g_Ohi);
    cudaGetSymbolAddress((void**)&pOlo,g_Olo);
    cudaGetSymbolAddress((void**)&pWhi,g_Whi);
    cudaGetSymbolAddress((void**)&pWlo,g_Wlo);
    cudaGetSymbolAddress((void**)&pMFhi,g_MFhi);
    cudaGetSymbolAddress((void**)&pMFlo,g_MFlo);
    cudaGetSymbolAddress((void**)&pG1hi,g_G1hi);
    cudaGetSymbolAddress((void**)&pG1lo,g_G1lo);

    cudaFuncSetAttribute(mma_gemm2_kernel, cudaFuncAttributeMaxDynamicSharedMemorySize, 2*BUFB);
    cudaFuncSetAttribute(attn_mma_kernel, cudaFuncAttributeMaxDynamicSharedMemorySize, ATT_SMEM);

    prep_weights_kernel<<<(WTOT+255)/256,256>>>(pe_w2,wq,wk,wv,wo,d_w1,d_w2,bk,bv);
    mm_kernel<<<64,256>>>(coord);
    pe_stage1_kernel<<<NTOT/8,256>>>(coord, pe_w1, pe_b1, pe_g, pe_be);
    // X = G @ w2^T + b2 (+enc/mtok) -> fp32 X + Xhi/Xlo
    mma_gemm2_kernel<<<dim3(NTOT/128,2),256,2*BUFB>>>(pGhi,pGlo,0,0, pWhi+WOFF_PE2,pWlo+WOFF_PE2, pe_b2,
                                                      pX,pXhi,pXlo, 0,0, 0,1,8,DIM,0, encoded,mask_token);
    // Q (hi/lo only)
    mma_gemm2_kernel<<<dim3(NM/128,2),256,2*BUFB>>>(pXhi,pXlo,0,0, pWhi+WOFF_Q,pWlo+WOFF_Q, bq,
                                                    0,pQhi,pQlo, 0,0, 1,0,8,DIM,0, 0,0);
    // K (hi/lo) + V (hi/lo) merged: 512 output cols
    mma_gemm2_kernel<<<dim3(NV/128,4),256,2*BUFB>>>(pXhi,pXlo,0,0, pWhi+WOFF_K,pWlo+WOFF_K, pBKV,
                                                    0,pKhi,pKlo, pVhi,pVlo, 2,0,8,DIM,1, 0,0);
    attn_mma_kernel<<<dim3(MSK/128,NHEAD,NB),256,ATT_SMEM>>>();
    // AO = O @ wo^T + bo
    mma_gemm2_kernel<<<dim3(NM/128,2),256,2*BUFB>>>(pOhi,pOlo,0,0, pWhi+WOFF_O,pWlo+WOFF_O, bo,
                                                    pAO,0,0, 0,0, 0,0,8,DIM,0, 0,0);
    mf_ln_kernel<<<NM/8,256>>>(an_g, an_b);
    // decoder
    mma_gemm2_kernel<<<dim3(NTOT/128,1),256,2*BUFB>>>(pXhi,pXlo,pMFhi,pMFlo, pWhi+WOFF_D1,pWlo+WOFF_D1, d_b1,
                                                      pH1,0,0, 0,0, 3,0,8,HID,0, 0,0);
    ln_gelu_kernel<<<NTOT/8,256>>>(d_g, d_be);
    mma_gemm2_kernel<<<dim3(NTOT/128,1),256,2*BUFB>>>(pG1hi,pG1lo,0,0, pWhi+WOFF_D2,pWlo+WOFF_D2, d_b2,
                                                      pH2,0,0, 0,0, 0,2,4,HID,0, 0,0);
    final_kernel<<<NTOT/8,256>>>(d_w3, d_b3, out);
}

// round 16
// speedup vs baseline: 1.4715x; 1.4715x over previous
#include <cuda_runtime.h>
#include <cuda_bf16.h>
#include <math.h>
#include <stdint.h>

typedef unsigned long long ull;
typedef unsigned int uint;
typedef __nv_bfloat16 bf16;

// Problem constants
#define NTOT  32768
#define DIM   256
#define NB    16
#define VIS   512
#define MSK   1536
#define NV    (NB*VIS)   // 8192
#define NM    (NB*MSK)   // 24576
#define HID   128
#define NHEAD 8
#define DH    32

// weight hi/lo layout offsets (elements)
#define WOFF_PE2 0
#define WOFF_Q   65536
#define WOFF_K   131072
#define WOFF_V   196608
#define WOFF_O   262144
#define WOFF_D1  327680          // 128x256
#define WOFF_D2  360448          // 128x128
#define WTOT     376832

// ---------------- scratch -----------------------------------------------------
__device__ float g_X[NTOT*DIM];
__device__ float g_AO[NM*DIM];
__device__ float g_H1[NTOT*HID];
__device__ float g_H2[NTOT*HID];
__device__ float g_biasKV[512];
__device__ int   g_mm[6];
__device__ bf16 g_Ghi[NTOT*DIM], g_Glo[NTOT*DIM];
__device__ bf16 g_Xhi[NTOT*DIM], g_Xlo[NTOT*DIM];
__device__ bf16 g_Qhi[NM*DIM],  g_Qlo[NM*DIM];
__device__ bf16 g_Khi[NV*DIM],  g_Klo[NV*DIM];
__device__ bf16 g_Vhi[NV*DIM],  g_Vlo[NV*DIM];
__device__ bf16 g_Ohi[NM*DIM],  g_Olo[NM*DIM];
__device__ bf16 g_MFhi[NM*DIM], g_MFlo[NM*DIM];
__device__ bf16 g_G1hi[NTOT*HID], g_G1lo[NTOT*HID];
__device__ bf16 g_Whi[WTOT], g_Wlo[WTOT];

// ---------------- helpers -----------------------------------------------------
__device__ __forceinline__ int f2ord(float f){ int i=__float_as_int(f); return i>=0 ? i : (i^0x7fffffff); }
__device__ __forceinline__ float ord2f(int i){ return __int_as_float(i>=0 ? i : (i^0x7fffffff)); }
__device__ __forceinline__ float gelu(float x){ return 0.5f*x*(1.0f+erff(x*0.70710678118654752f)); }
__device__ __forceinline__ uint pkbf(float a, float b){
    __nv_bfloat162 t=__floats2bfloat162_rn(a,b); return *(uint*)&t;
}
__device__ __forceinline__ uint32_t smem_u32(const void* p){
    uint32_t a; asm("{ .reg .u64 t; cvta.to.shared.u64 t, %1; cvt.u32.u64 %0, t; }" : "=r"(a) : "l"(p)); return a;
}
#define LDM4(r0,r1,r2,r3,addr) \
    asm volatile("ldmatrix.sync.aligned.m8n8.x4.shared.b16 {%0,%1,%2,%3}, [%4];" \
        : "=r"(r0),"=r"(r1),"=r"(r2),"=r"(r3) : "r"(addr))
#define LDM4T(r0,r1,r2,r3,addr) \
    asm volatile("ldmatrix.sync.aligned.m8n8.x4.trans.shared.b16 {%0,%1,%2,%3}, [%4];" \
        : "=r"(r0),"=r"(r1),"=r"(r2),"=r"(r3) : "r"(addr))
#define MMA16816(d, a, b) \
    asm volatile("mma.sync.aligned.m16n8k16.row.col.f32.bf16.bf16.f32 " \
        "{%0,%1,%2,%3}, {%4,%5,%6,%7}, {%8,%9}, {%0,%1,%2,%3};" \
        : "+f"((d)[0]),"+f"((d)[1]),"+f"((d)[2]),"+f"((d)[3]) \
        : "r"((a)[0]),"r"((a)[1]),"r"((a)[2]),"r"((a)[3]),"r"((b)[0]),"r"((b)[1]))
#define CPA16(dst,src) asm volatile("cp.async.cg.shared.global [%0], [%1], 16;"::"r"(dst),"l"(src))
#define CPCOMMIT() asm volatile("cp.async.commit_group;")
#define CPWAIT1() asm volatile("cp.async.wait_group 1;")
#define CPWAIT0() asm volatile("cp.async.wait_group 0;")

// ================= min/max reduction =========================================
__global__ void mm_kernel(const float* __restrict__ coord){
    float mn0=1e30f,mn1=1e30f,mn2=1e30f,mx0=-1e30f,mx1=-1e30f,mx2=-1e30f;
    for(int p=blockIdx.x*blockDim.x+threadIdx.x; p<NTOT; p+=gridDim.x*blockDim.x){
        float a=coord[p*3+0], b=coord[p*3+1], c=coord[p*3+2];
        mn0=fminf(mn0,a); mx0=fmaxf(mx0,a);
        mn1=fminf(mn1,b); mx1=fmaxf(mx1,b);
        mn2=fminf(mn2,c); mx2=fmaxf(mx2,c);
    }
    for(int o=16;o;o>>=1){
        mn0=fminf(mn0,__shfl_xor_sync(0xffffffffu,mn0,o));
        mn1=fminf(mn1,__shfl_xor_sync(0xffffffffu,mn1,o));
        mn2=fminf(mn2,__shfl_xor_sync(0xffffffffu,mn2,o));
        mx0=fmaxf(mx0,__shfl_xor_sync(0xffffffffu,mx0,o));
        mx1=fmaxf(mx1,__shfl_xor_sync(0xffffffffu,mx1,o));
        mx2=fmaxf(mx2,__shfl_xor_sync(0xffffffffu,mx2,o));
    }
    if((threadIdx.x&31)==0){
        atomicMin(&g_mm[0],f2ord(mn0)); atomicMin(&g_mm[1],f2ord(mn1)); atomicMin(&g_mm[2],f2ord(mn2));
        atomicMax(&g_mm[3],f2ord(mx0)); atomicMax(&g_mm[4],f2ord(mx1)); atomicMax(&g_mm[5],f2ord(mx2));
    }
}

// ================= weight prep (+ g_mm init) ==================================
__global__ void prep_weights_kernel(const float* __restrict__ w2, const float* __restrict__ wq,
                                    const float* __restrict__ wk, const float* __restrict__ wv,
                                    const float* __restrict__ wo, const float* __restrict__ dw1,
                                    const float* __restrict__ dw2,
                                    const float* __restrict__ bk, const float* __restrict__ bv){
    int i=blockIdx.x*blockDim.x+threadIdx.x;
    if(i<3) g_mm[i]=0x7fffffff;
    else if(i<6) g_mm[i]=0x80000000;
    if(i<512) g_biasKV[i] = (i<256)? bk[i] : bv[i-256];
    if(i>=WTOT) return;
    const float* src; int j;
    if(i<WOFF_Q){ src=w2; j=i; }
    else if(i<WOFF_K){ src=wq; j=i-WOFF_Q; }
    else if(i<WOFF_V){ src=wk; j=i-WOFF_K; }
    else if(i<WOFF_O){ src=wv; j=i-WOFF_V; }
    else if(i<WOFF_D1){ src=wo; j=i-WOFF_O; }
    else if(i<WOFF_D2){ src=dw1; j=i-WOFF_D1; }
    else { src=dw2; j=i-WOFF_D2; }
    float x=src[j];
    bf16 h=__float2bfloat16_rn(x);
    g_Whi[i]=h;
    g_Wlo[i]=__float2bfloat16_rn(x-__bfloat162float(h));
}

// ================= pos-embed stage 1 =========================================
__global__ void pe_stage1_kernel(const float* __restrict__ coord,
                                 const float* __restrict__ w1, const float* __restrict__ b1,
                                 const float* __restrict__ gam, const float* __restrict__ bet){
    int w=threadIdx.x>>5, lane=threadIdx.x&31;
    int p=blockIdx.x*8+w;
    float lo0=ord2f(g_mm[0]), lo1=ord2f(g_mm[1]), lo2=ord2f(g_mm[2]);
    float s0=fmaxf(ord2f(g_mm[3])-lo0,1.0f);
    float s1=fmaxf(ord2f(g_mm[4])-lo1,1.0f);
    float s2=fmaxf(ord2f(g_mm[5])-lo2,1.0f);
    float c0=(coord[p*3+0]-lo0)/s0;
    float c1=(coord[p*3+1]-lo1)/s1;
    float c2=(coord[p*3+2]-lo2)/s2;
    float v[8]; float s=0.f, ss=0.f;
#pragma unroll
    for(int j=0;j<8;j++){
        int d=lane+32*j;
        float h=c0*w1[d*3+0]+c1*w1[d*3+1]+c2*w1[d*3+2]+b1[d];
        v[j]=h; s+=h; ss+=h*h;
    }
    for(int o=16;o;o>>=1){ s+=__shfl_xor_sync(0xffffffffu,s,o); ss+=__shfl_xor_sync(0xffffffffu,ss,o); }
    float mean=s*(1.0f/256.0f);
    float rstd=rsqrtf(ss*(1.0f/256.0f)-mean*mean+1e-5f);
#pragma unroll
    for(int j=0;j<8;j++){
        int d=lane+32*j;
        float t=(v[j]-mean)*rstd*gam[d]+bet[d];
        float g=gelu(t);
        bf16 h=__float2bfloat16_rn(g);
        g_Ghi[(size_t)p*DIM+d]=h;
        g_Glo[(size_t)p*DIM+d]=__float2bfloat16_rn(g-__bfloat162float(h));
    }
}

// ================= bf16x3 mma GEMM (3-stage pipeline, 1 CTA/SM) ==============
// gatherMode: 0 direct, 1 masked idx, 2 visible idx, 3 mixed X/MF (decoder)
// epiMode: 0 plain, 1 +enc/mtok, 2 gelu
// kvSplit: cols>=256 route hi/lo to vhi/vlo (stride 256), cols<256 -> Chi/Clo
#define KSTR 40
#define TILEB (128*KSTR*2)
#define BUFB  (4*TILEB)
__global__ void __launch_bounds__(256,1) mma_gemm2_kernel(
        const bf16* __restrict__ Ahi, const bf16* __restrict__ Alo,
        const bf16* __restrict__ A2hi, const bf16* __restrict__ A2lo,
        const bf16* __restrict__ Bhi, const bf16* __restrict__ Blo,
        const float* __restrict__ bias, float* __restrict__ Cf,
        bf16* __restrict__ Chi, bf16* __restrict__ Clo,
        bf16* __restrict__ vhi, bf16* __restrict__ vlo,
        int gatherMode, int epiMode, int kchunks, int strideC, int kvSplit,
        const float* __restrict__ encoded, const float* __restrict__ mtok){
    extern __shared__ char dsm[];
    const int tid=threadIdx.x, lane=tid&31, wid=tid>>5;
    const int m0=blockIdx.x*128, n0=blockIdx.y*128;
    const int wm=(wid>>2)*64, wn=(wid&3)*32;
    const int K=kchunks*32;

    const int lrow=tid>>1, hc=(tid&1)*16;
    int cm=m0+lrow;
    const bf16 *aH, *aL;
    if(gatherMode==1){ int r=(cm/1536)*2048+512+(cm%1536); aH=Ahi+(size_t)r*K+hc; aL=Alo+(size_t)r*K+hc; }
    else if(gatherMode==2){ int r=(cm>>9)*2048+(cm&511); aH=Ahi+(size_t)r*K+hc; aL=Alo+(size_t)r*K+hc; }
    else if(gatherMode==3){
        int off=cm&2047;
        if(off<VIS){ aH=Ahi+(size_t)cm*K+hc; aL=Alo+(size_t)cm*K+hc; }
        else { int r=(cm>>11)*MSK+off-VIS; aH=A2hi+(size_t)r*K+hc; aL=A2lo+(size_t)r*K+hc; }
    }
    else { aH=Ahi+(size_t)cm*K+hc; aL=Alo+(size_t)cm*K+hc; }
    const bf16* bH=Bhi+(size_t)(n0+lrow)*K+hc;
    const bf16* bL=Blo+(size_t)(n0+lrow)*K+hc;
    const uint32_t sbase=smem_u32(dsm);
    const uint32_t st_off=(uint32_t)((lrow*KSTR+hc)*2);

    const int a_r=wm+(lane&7)+((lane>>3)&1)*8;
    const int a_c=(lane>>4)*8;
    const int b_r=wn+(lane&7)+(lane>>4)*8;
    const int b_c=((lane>>3)&1)*8;

    float acc[4][4][4];
#pragma unroll
    for(int i=0;i<4;i++)
#pragma unroll
        for(int j=0;j<4;j++)
#pragma unroll
            for(int k=0;k<4;k++) acc[i][j][k]=0.f;

#define LOAD_CHUNK(c,buf) do{ \
        uint32_t b0=sbase+(buf)*BUFB; \
        const bf16* p0=aH+(c)*32; CPA16(b0+st_off,p0); CPA16(b0+st_off+16,p0+8); \
        const bf16* p1=aL+(c)*32; CPA16(b0+TILEB+st_off,p1); CPA16(b0+TILEB+st_off+16,p1+8); \
        const bf16* p2=bH+(c)*32; CPA16(b0+2*TILEB+st_off,p2); CPA16(b0+2*TILEB+st_off+16,p2+8); \
        const bf16* p3=bL+(c)*32; CPA16(b0+3*TILEB+st_off,p3); CPA16(b0+3*TILEB+st_off+16,p3+8); \
        CPCOMMIT(); }while(0)

    LOAD_CHUNK(0,0);
    if(kchunks>1) LOAD_CHUNK(1,1);
    int buf=0;
    for(int c=0;c<kchunks;c++){
        if(c+1<kchunks) CPWAIT1(); else CPWAIT0();
        __syncthreads();
        if(c+2<kchunks){
            int nb=buf+2; if(nb>=3) nb-=3;
            LOAD_CHUNK(c+2,nb);
        }
        uint32_t b0=sbase+buf*BUFB;
#pragma unroll
        for(int ks=0;ks<2;ks++){
            uint bh[4][2], bl[4][2];
#pragma unroll
            for(int bt=0;bt<2;bt++){
                uint32_t off=(uint32_t)(((b_r+bt*16)*KSTR + b_c + ks*16)*2);
                uint r0,r1,r2,r3;
                LDM4(r0,r1,r2,r3, b0+2*TILEB+off);
                bh[2*bt][0]=r0; bh[2*bt][1]=r1; bh[2*bt+1][0]=r2; bh[2*bt+1][1]=r3;
                LDM4(r0,r1,r2,r3, b0+3*TILEB+off);
                bl[2*bt][0]=r0; bl[2*bt][1]=r1; bl[2*bt+1][0]=r2; bl[2*bt+1][1]=r3;
            }
#pragma unroll
            for(int mt=0;mt<4;mt++){
                uint ah[4], al[4];
                uint32_t off=(uint32_t)(((a_r+mt*16)*KSTR + a_c + ks*16)*2);
                LDM4(ah[0],ah[1],ah[2],ah[3], b0+off);
                LDM4(al[0],al[1],al[2],al[3], b0+TILEB+off);
#pragma unroll
                for(int nt=0;nt<4;nt++){
                    MMA16816(acc[mt][nt], ah, bh[nt]);
                    MMA16816(acc[mt][nt], ah, bl[nt]);
                    MMA16816(acc[mt][nt], al, bh[nt]);
                }
            }
        }
        buf++; if(buf>=3) buf=0;
    }
#undef LOAD_CHUNK

#pragma unroll
    for(int mt=0;mt<4;mt++){
        int r0=m0+wm+mt*16+(lane>>2);
        int r1=r0+8;
        const float *ap0=0,*ap1=0;
        if(epiMode==1){
            int off0=r0&2047; ap0=(off0<VIS)? encoded+(size_t)((r0>>11)*VIS+off0)*DIM : mtok;
            int off1=r1&2047; ap1=(off1<VIS)? encoded+(size_t)((r1>>11)*VIS+off1)*DIM : mtok;
        }
#pragma unroll
        for(int nt=0;nt<4;nt++){
            int cc=n0+wn+nt*8+(lane&3)*2;
            float b0v=bias[cc], b1v=bias[cc+1];
            float v00=acc[mt][nt][0]+b0v, v01=acc[mt][nt][1]+b1v;
            float v10=acc[mt][nt][2]+b0v, v11=acc[mt][nt][3]+b1v;
            if(epiMode==1){ v00+=ap0[cc]; v01+=ap0[cc+1]; v10+=ap1[cc]; v11+=ap1[cc+1]; }
            else if(epiMode==2){ v00=gelu(v00); v01=gelu(v01); v10=gelu(v10); v11=gelu(v11); }
            bf16* dhi=Chi; bf16* dlo=Clo; int wc=cc;
            if(kvSplit && n0>=256){ dhi=vhi; dlo=vlo; wc=cc-256; }
            else if(Cf){
                *(float2*)(Cf+(size_t)r0*strideC+cc)=make_float2(v00,v01);
                *(float2*)(Cf+(size_t)r1*strideC+cc)=make_float2(v10,v11);
            }
            if(dhi){
                bf16 h00=__float2bfloat16_rn(v00), h01=__float2bfloat16_rn(v01);
                bf16 h10=__float2bfloat16_rn(v10), h11=__float2bfloat16_rn(v11);
                __nv_bfloat162 hp0; hp0.x=h00; hp0.y=h01;
                __nv_bfloat162 hp1; hp1.x=h10; hp1.y=h11;
                *(__nv_bfloat162*)(dhi+(size_t)r0*strideC+wc)=hp0;
                *(__nv_bfloat162*)(dhi+(size_t)r1*strideC+wc)=hp1;
                __nv_bfloat162 lp0, lp1;
                lp0.x=__float2bfloat16_rn(v00-__bfloat162float(h00));
                lp0.y=__float2bfloat16_rn(v01-__bfloat162float(h01));
                lp1.x=__float2bfloat16_rn(v10-__bfloat162float(h10));
                lp1.y=__float2bfloat16_rn(v11-__bfloat162float(h11));
                *(__nv_bfloat162*)(dlo+(size_t)r0*strideC+wc)=lp0;
                *(__nv_bfloat162*)(dlo+(size_t)r1*strideC+wc)=lp1;
            }
        }
    }
}

// ================= mma flash attention (cp.async double-buffered K/V) =========
#define QPAD 40
#define VP   40
#define SOFF_QH 0
#define SOFF_QL 10240
#define ABUF0   20480
#define ABUFSZ  40960          // KH,KL,VH,VL each 10240
#define ATT_SMEM (ABUF0+2*ABUFSZ)   // 102400
#define ATT_SCALE 0.17677669529663687f
__global__ void __launch_bounds__(256,1) attn_mma_kernel(){
    extern __shared__ char dsm[];
    const int tid=threadIdx.x, lane=tid&31, wid=tid>>5;
    const int qt=blockIdx.x, h=blockIdx.y, b=blockIdx.z;
    const uint32_t sb=smem_u32(dsm);

    const int srow=tid>>1, shalf=tid&1;
    const uint soff=(uint)((srow*QPAD+shalf*16)*2);

#define ATT_LOAD(kt,buf) do{ \
        size_t g=(size_t)(b*VIS+(kt)*128+srow)*DIM + h*DH + shalf*16; \
        uint32_t bb=sb+ABUF0+(buf)*ABUFSZ; \
        const bf16* k0=g_Khi+g; CPA16(bb+soff,k0); CPA16(bb+soff+16,k0+8); \
        const bf16* k1=g_Klo+g; CPA16(bb+10240+soff,k1); CPA16(bb+10240+soff+16,k1+8); \
        const bf16* v0=g_Vhi+g; CPA16(bb+20480+soff,v0); CPA16(bb+20480+soff+16,v0+8); \
        const bf16* v1=g_Vlo+g; CPA16(bb+30720+soff,v1); CPA16(bb+30720+soff+16,v1+8); \
        CPCOMMIT(); }while(0)

    // stage Q (plain stores) + prefetch kt=0
    {
        size_t g=(size_t)(b*MSK+qt*128+srow)*DIM + h*DH + shalf*16;
        const uint4* s0=(const uint4*)(g_Qhi+g);
        uint4* d0=(uint4*)(dsm+SOFF_QH+soff); d0[0]=s0[0]; d0[1]=s0[1];
        const uint4* s1=(const uint4*)(g_Qlo+g);
        uint4* d1=(uint4*)(dsm+SOFF_QL+soff); d1[0]=s1[0]; d1[1]=s1[1];
    }
    ATT_LOAD(0,0);
    __syncthreads();

    const int wm=wid*16;
    const int a_r=wm+(lane&7)+((lane>>3)&1)*8;
    const int a_c=(lane>>4)*8;
    uint qh[2][4], ql[2][4];
#pragma unroll
    for(int ks=0;ks<2;ks++){
        uint off=(uint)((a_r*QPAD + a_c + ks*16)*2);
        LDM4(qh[ks][0],qh[ks][1],qh[ks][2],qh[ks][3], sb+SOFF_QH+off);
        LDM4(ql[ks][0],ql[ks][1],ql[ks][2],ql[ks][3], sb+SOFF_QL+off);
    }

    const int b_r=(lane&7)+(lane>>4)*8;
    const int b_c=((lane>>3)&1)*8;
    const int v_r=(lane&7)+((lane>>3)&1)*8;
    const int v_c=(lane>>4)*8;
    float accO[4][4];
#pragma unroll
    for(int i=0;i<4;i++)
#pragma unroll
        for(int j=0;j<4;j++) accO[i][j]=0.f;
    float l0=0.f, l1=0.f;
    int buf=0;

    for(int kt=0;kt<4;kt++){
        CPWAIT0();
        __syncthreads();
        if(kt<3) ATT_LOAD(kt+1,buf^1);
        uint32_t kb=sb+ABUF0+buf*ABUFSZ;

        float acc[16][4];
#pragma unroll
        for(int i=0;i<16;i++)
#pragma unroll
            for(int j=0;j<4;j++) acc[i][j]=0.f;
#pragma unroll
        for(int ks=0;ks<2;ks++){
#pragma unroll
            for(int bt=0;bt<8;bt++){
                uint off=(uint)(((b_r+bt*16)*QPAD + b_c + ks*16)*2);
                uint kh0[2],kh1[2],kl0[2],kl1[2];
                { uint r0,r1,r2,r3; LDM4(r0,r1,r2,r3, kb+off);
                  kh0[0]=r0; kh0[1]=r1; kh1[0]=r2; kh1[1]=r3; }
                { uint r0,r1,r2,r3; LDM4(r0,r1,r2,r3, kb+10240+off);
                  kl0[0]=r0; kl0[1]=r1; kl1[0]=r2; kl1[1]=r3; }
                MMA16816(acc[2*bt],   qh[ks], kh0);
                MMA16816(acc[2*bt],   qh[ks], kl0);
                MMA16816(acc[2*bt],   ql[ks], kh0);
                MMA16816(acc[2*bt+1], qh[ks], kh1);
                MMA16816(acc[2*bt+1], qh[ks], kl1);
                MMA16816(acc[2*bt+1], ql[ks], kh1);
            }
        }
#pragma unroll
        for(int k2=0;k2<8;k2++){
            float p[8];
#pragma unroll
            for(int j=0;j<4;j++) p[j]  =__expf(fminf(acc[2*k2][j]  *ATT_SCALE,80.f));
#pragma unroll
            for(int j=0;j<4;j++) p[4+j]=__expf(fminf(acc[2*k2+1][j]*ATT_SCALE,80.f));
            l0 += p[0]+p[1]+p[4]+p[5];
            l1 += p[2]+p[3]+p[6]+p[7];
            uint ph[4], pl[4];
            ph[0]=pkbf(p[0],p[1]); ph[1]=pkbf(p[2],p[3]);
            ph[2]=pkbf(p[4],p[5]); ph[3]=pkbf(p[6],p[7]);
            float r[8];
#pragma unroll
            for(int j=0;j<8;j++){
                bf16 hh=__float2bfloat16_rn(p[j]);
                r[j]=p[j]-__bfloat162float(hh);
            }
            pl[0]=pkbf(r[0],r[1]); pl[1]=pkbf(r[2],r[3]);
            pl[2]=pkbf(r[4],r[5]); pl[3]=pkbf(r[6],r[7]);
            uint vh2[4][2], vl2[4][2];
#pragma unroll
            for(int nh=0;nh<2;nh++){
                uint off=(uint)(((v_r+k2*16)*VP + v_c + nh*16)*2);
                uint r0,r1,r2,r3;
                LDM4T(r0,r1,r2,r3, kb+20480+off);
                vh2[2*nh][0]=r0; vh2[2*nh][1]=r1; vh2[2*nh+1][0]=r2; vh2[2*nh+1][1]=r3;
                LDM4T(r0,r1,r2,r3, kb+30720+off);
                vl2[2*nh][0]=r0; vl2[2*nh][1]=r1; vl2[2*nh+1][0]=r2; vl2[2*nh+1][1]=r3;
            }
#pragma unroll
            for(int nt=0;nt<4;nt++){
                MMA16816(accO[nt], ph, vh2[nt]);
                MMA16816(accO[nt], ph, vl2[nt]);
                MMA16816(accO[nt], pl, vh2[nt]);
            }
        }
        buf^=1;
    }
#undef ATT_LOAD

    l0 += __shfl_xor_sync(0xffffffffu,l0,1); l0 += __shfl_xor_sync(0xffffffffu,l0,2);
    l1 += __shfl_xor_sync(0xffffffffu,l1,1); l1 += __shfl_xor_sync(0xffffffffu,l1,2);
    float inv0=1.0f/l0, inv1=1.0f/l1;
    int row0=b*MSK+qt*128+wm+(lane>>2);
    int row1=row0+8;
#pragma unroll
    for(int nt=0;nt<4;nt++){
        int col=h*DH+nt*8+(lane&3)*2;
        float v00=accO[nt][0]*inv0, v01=accO[nt][1]*inv0;
        float v10=accO[nt][2]*inv1, v11=accO[nt][3]*inv1;
        bf16 h00=__float2bfloat16_rn(v00), h01=__float2bfloat16_rn(v01);
        bf16 h10=__float2bfloat16_rn(v10), h11=__float2bfloat16_rn(v11);
        __nv_bfloat162 hp0; hp0.x=h00; hp0.y=h01;
        __nv_bfloat162 hp1; hp1.x=h10; hp1.y=h11;
        *(__nv_bfloat162*)(g_Ohi+(size_t)row0*DIM+col)=hp0;
        *(__nv_bfloat162*)(g_Ohi+(size_t)row1*DIM+col)=hp1;
        __nv_bfloat162 lp0, lp1;
        lp0.x=__float2bfloat16_rn(v00-__bfloat162float(h00));
        lp0.y=__float2bfloat16_rn(v01-__bfloat162float(h01));
        lp1.x=__float2bfloat16_rn(v10-__bfloat162float(h10));
        lp1.y=__float2bfloat16_rn(v11-__bfloat162float(h11));
        *(__nv_bfloat162*)(g_Olo+(size_t)row0*DIM+col)=lp0;
        *(__nv_bfloat162*)(g_Olo+(size_t)row1*DIM+col)=lp1;
    }
}

// ================= residual LN -> MF hi/lo ====================================
__global__ void mf_ln_kernel(const float* __restrict__ gam, const float* __restrict__ bet){
    int w=threadIdx.x>>5, lane=threadIdx.x&31;
    int row=blockIdx.x*8+w;
    int pt=(row/1536)*2048+512+(row%1536);
    float v[8]; float s=0.f, ss=0.f;
#pragma unroll
    for(int j=0;j<8;j++){
        int d=lane+32*j;
        float x=g_X[(size_t)pt*DIM+d]+g_AO[(size_t)row*DIM+d];
        v[j]=x; s+=x; ss+=x*x;
    }
    for(int o=16;o;o>>=1){ s+=__shfl_xor_sync(0xffffffffu,s,o); ss+=__shfl_xor_sync(0xffffffffu,ss,o); }
    float mean=s*(1.0f/256.0f);
    float rstd=rsqrtf(ss*(1.0f/256.0f)-mean*mean+1e-5f);
#pragma unroll
    for(int j=0;j<8;j++){
        int d=lane+32*j;
        float t=(v[j]-mean)*rstd*gam[d]+bet[d];
        bf16 h=__float2bfloat16_rn(t);
        g_MFhi[(size_t)row*DIM+d]=h;
        g_MFlo[(size_t)row*DIM+d]=__float2bfloat16_rn(t-__bfloat162float(h));
    }
}

// ================= decoder stage: LN(H1)+gelu -> G1 hi/lo =====================
__global__ void ln_gelu_kernel(const float* __restrict__ gam, const float* __restrict__ bet){
    int w=threadIdx.x>>5, lane=threadIdx.x&31;
    int row=blockIdx.x*8+w;
    float4 v=((const float4*)(g_H1+(size_t)row*HID))[lane];
    float s=v.x+v.y+v.z+v.w;
    float ss=v.x*v.x+v.y*v.y+v.z*v.z+v.w*v.w;
    for(int o=16;o;o>>=1){ s+=__shfl_xor_sync(0xffffffffu,s,o); ss+=__shfl_xor_sync(0xffffffffu,ss,o); }
    float mean=s*(1.0f/128.0f);
    float rstd=rsqrtf(ss*(1.0f/128.0f)-mean*mean+1e-5f);
    float g4[4]; float vv[4]={v.x,v.y,v.z,v.w};
#pragma unroll
    for(int j=0;j<4;j++){
        int d=lane*4+j;
        g4[j]=gelu((vv[j]-mean)*rstd*gam[d]+bet[d]);
    }
    bf16* hp=g_G1hi+(size_t)row*HID+lane*4;
    bf16* lp=g_G1lo+(size_t)row*HID+lane*4;
#pragma unroll
    for(int j=0;j<2;j++){
        __nv_bfloat162 h2v, l2v;
        float a=g4[2*j], b2=g4[2*j+1];
        bf16 ha=__float2bfloat16_rn(a), hb=__float2bfloat16_rn(b2);
        h2v.x=ha; h2v.y=hb;
        l2v.x=__float2bfloat16_rn(a-__bfloat162float(ha));
        l2v.y=__float2bfloat16_rn(b2-__bfloat162float(hb));
        *(__nv_bfloat162*)(hp+2*j)=h2v;
        *(__nv_bfloat162*)(lp+2*j)=l2v;
    }
}

// ================= final: out = H2 @ w3^T + b3 ================================
__global__ void final_kernel(const float* __restrict__ w3, const float* __restrict__ b3,
                             float* __restrict__ out){
    int w=threadIdx.x>>5, lane=threadIdx.x&31;
    int p=blockIdx.x*8+w;
    const float* h2=g_H2+(size_t)p*HID;
    float x0=h2[lane], x1=h2[lane+32], x2=h2[lane+64], x3=h2[lane+96];
    float q[4];
#pragma unroll
    for(int j=0;j<4;j++){
        const float* wj=w3+j*HID;
        q[j]=x0*wj[lane]+x1*wj[lane+32]+x2*wj[lane+64]+x3*wj[lane+96];
        for(int o=16;o;o>>=1) q[j]+=__shfl_xor_sync(0xffffffffu,q[j],o);
    }
    if(lane==0)
        *(float4*)(out+(size_t)p*4)=make_float4(q[0]+b3[0],q[1]+b3[1],q[2]+b3[2],q[3]+b3[3]);
}

// -----------------------------------------------------------------------------
extern "C" void kernel_launch(void* const* d_in, const int* in_sizes, int n_in,
                              void* d_out, int out_size){
    const float* encoded   =(const float*)d_in[0];
    const float* coord     =(const float*)d_in[1];
    const float* mask_token=(const float*)d_in[2];
    const float* pe_w1     =(const float*)d_in[3];
    const float* pe_b1     =(const float*)d_in[4];
    const float* pe_g      =(const float*)d_in[5];
    const float* pe_be     =(const float*)d_in[6];
    const float* pe_w2     =(const float*)d_in[7];
    const float* pe_b2     =(const float*)d_in[8];
    const float* wq        =(const float*)d_in[9];
    const float* bq        =(const float*)d_in[10];
    const float* wk        =(const float*)d_in[11];
    const float* bk        =(const float*)d_in[12];
    const float* wv        =(const float*)d_in[13];
    const float* bv        =(const float*)d_in[14];
    const float* wo        =(const float*)d_in[15];
    const float* bo        =(const float*)d_in[16];
    const float* an_g      =(const float*)d_in[17];
    const float* an_b      =(const float*)d_in[18];
    const float* d_w1      =(const float*)d_in[19];
    const float* d_b1      =(const float*)d_in[20];
    const float* d_g       =(const float*)d_in[21];
    const float* d_be      =(const float*)d_in[22];
    const float* d_w2      =(const float*)d_in[23];
    const float* d_b2      =(const float*)d_in[24];
    const float* d_w3      =(const float*)d_in[25];
    const float* d_b3      =(const float*)d_in[26];
    float* out=(float*)d_out;
    (void)in_sizes; (void)n_in; (void)out_size;

    float *pX=0,*pAO=0,*pH1=0,*pH2=0,*pBKV=0;
    bf16 *pGhi=0,*pGlo=0,*pXhi=0,*pXlo=0,*pQhi=0,*pQlo=0,*pKhi=0,*pKlo=0,*pVhi=0,*pVlo=0;
    bf16 *pOhi=0,*pOlo=0,*pWhi=0,*pWlo=0,*pMFhi=0,*pMFlo=0,*pG1hi=0,*pG1lo=0;
    cudaGetSymbolAddress((void**)&pX,  g_X);
    cudaGetSymbolAddress((void**)&pAO, g_AO);
    cudaGetSymbolAddress((void**)&pH1, g_H1);
    cudaGetSymbolAddress((void**)&pH2, g_H2);
    cudaGetSymbolAddress((void**)&pBKV,g_biasKV);
    cudaGetSymbolAddress((void**)&pGhi,g_Ghi);
    cudaGetSymbolAddress((void**)&pGlo,g_Glo);
    cudaGetSymbolAddress((void**)&pXhi,g_Xhi);
    cudaGetSymbolAddress((void**)&pXlo,g_Xlo);
    cudaGetSymbolAddress((void**)&pQhi,g_Qhi);
    cudaGetSymbolAddress((void**)&pQlo,g_Qlo);
    cudaGetSymbolAddress((void**)&pKhi,g_Khi);
    cudaGetSymbolAddress((void**)&pKlo,g_Klo);
    cudaGetSymbolAddress((void**)&pVhi,g_Vhi);
    cudaGetSymbolAddress((void**)&pVlo,g_Vlo);
    cudaGetSymbolAddress((void**)&pOhi,g_Ohi);
    cudaGetSymbolAddress((void**)&pOlo,g_Olo);
    cudaGetSymbolAddress((void**)&pWhi,g_Whi);
    cudaGetSymbolAddress((void**)&pWlo,g_Wlo);
    cudaGetSymbolAddress((void**)&pMFhi,g_MFhi);
    cudaGetSymbolAddress((void**)&pMFlo,g_MFlo);
    cudaGetSymbolAddress((void**)&pG1hi,g_G1hi);
    cudaGetSymbolAddress((void**)&pG1lo,g_G1lo);

    cudaFuncSetAttribute(mma_gemm2_kernel, cudaFuncAttributeMaxDynamicSharedMemorySize, 3*BUFB);
    cudaFuncSetAttribute(attn_mma_kernel, cudaFuncAttributeMaxDynamicSharedMemorySize, ATT_SMEM);

    prep_weights_kernel<<<(WTOT+255)/256,256>>>(pe_w2,wq,wk,wv,wo,d_w1,d_w2,bk,bv);
    mm_kernel<<<64,256>>>(coord);
    pe_stage1_kernel<<<NTOT/8,256>>>(coord, pe_w1, pe_b1, pe_g, pe_be);
    // X = G @ w2^T + b2 (+enc/mtok) -> fp32 X + Xhi/Xlo
    mma_gemm2_kernel<<<dim3(NTOT/128,2),256,3*BUFB>>>(pGhi,pGlo,0,0, pWhi+WOFF_PE2,pWlo+WOFF_PE2, pe_b2,
                                                      pX,pXhi,pXlo, 0,0, 0,1,8,DIM,0, encoded,mask_token);
    // Q (hi/lo only)
    mma_gemm2_kernel<<<dim3(NM/128,2),256,3*BUFB>>>(pXhi,pXlo,0,0, pWhi+WOFF_Q,pWlo+WOFF_Q, bq,
                                                    0,pQhi,pQlo, 0,0, 1,0,8,DIM,0, 0,0);
    // K (hi/lo) + V (hi/lo) merged: 512 output cols
    mma_gemm2_kernel<<<dim3(NV/128,4),256,3*BUFB>>>(pXhi,pXlo,0,0, pWhi+WOFF_K,pWlo+WOFF_K, pBKV,
                                                    0,pKhi,pKlo, pVhi,pVlo, 2,0,8,DIM,1, 0,0);
    attn_mma_kernel<<<dim3(MSK/128,NHEAD,NB),256,ATT_SMEM>>>();
    // AO = O @ wo^T + bo
    mma_gemm2_kernel<<<dim3(NM/128,2),256,3*BUFB>>>(pOhi,pOlo,0,0, pWhi+WOFF_O,pWlo+WOFF_O, bo,
                                                    pAO,0,0, 0,0, 0,0,8,DIM,0, 0,0);
    mf_ln_kernel<<<NM/8,256>>>(an_g, an_b);
    // decoder
    mma_gemm2_kernel<<<dim3(NTOT/128,1),256,3*BUFB>>>(pXhi,pXlo,pMFhi,pMFlo, pWhi+WOFF_D1,pWlo+WOFF_D1, d_b1,
                                                      pH1,0,0, 0,0, 3,0,8,HID,0, 0,0);
    ln_gelu_kernel<<<NTOT/8,256>>>(d_g, d_be);
    mma_gemm2_kernel<<<dim3(NTOT/128,1),256,3*BUFB>>>(pG1hi,pG1lo,0,0, pWhi+WOFF_D2,pWlo+WOFF_D2, d_b2,
                                                      pH2,0,0, 0,0, 0,2,4,HID,0, 0,0);
    final_kernel<<<NTOT/8,256>>>(d_w3, d_b3, out);
}